// round 5
// baseline (speedup 1.0000x reference)
#include <cuda_runtime.h>
#include <cuda_bf16.h>

// Problem shape (fixed): x = (2, 9, 64, 192, 192) f32
#define NPB   2359296              // voxels per batch = 64*192*192
#define NB    2
#define NVOX  (NB * NPB)           // 4,718,592
#define BLOCK 256
#define CHUNK 1024                 // voxels per stage (BLOCK threads x 4)
#define SPB   (NPB / CHUNK)        // 2304 stages per batch
#define TOTAL_STAGES (NVOX / CHUNK) // 4608
#define GRID  296                  // 2 CTAs per SM on 148 SMs
#define PIPE  3                    // pipeline depth (stage buffers)
#define STAGE_FLOATS (9 * CHUNK)   // floats per stage buffer
#define SMEM_BYTES (PIPE * STAGE_FLOATS * 4)  // 110,592 B

// Closed-form symmetric 3x3 eigenvalues (Smith's trigonometric method).
// Returns ascending e0 <= e1 <= e2.
__device__ __forceinline__ void eig3(
    float a00, float a01, float a02, float a11, float a12, float a22,
    float& e0, float& e1, float& e2)
{
    float q  = (a00 + a11 + a22) * (1.0f / 3.0f);
    float d0 = a00 - q, d1 = a11 - q, d2 = a22 - q;
    float off = a01 * a01 + a02 * a02 + a12 * a12;
    float p2  = d0 * d0 + d1 * d1 + d2 * d2 + 2.0f * off;
    p2 = fmaxf(p2, 1e-30f);                 // guard p2==0 (A == q*I)
    float p2s  = p2 * (1.0f / 6.0f);
    float pinv = rsqrtf(p2s);               // MUFU.RSQ
    float p    = p2s * pinv;                // sqrt(p2/6)

    float det = d0 * (d1 * d2 - a12 * a12)
              - a01 * (a01 * d2 - a12 * a02)
              + a02 * (a01 * a12 - d1 * a02);

    float pinv3 = pinv * pinv * pinv;
    float r = 0.5f * det * pinv3;           // det(B)/2, B=(A-qI)/p
    r = fminf(fmaxf(r, -1.0f), 1.0f);

    float theta = acosf(r) * (1.0f / 3.0f); // theta in [0, pi/3]
    float s, c;
    __sincosf(theta, &s, &c);               // s >= 0 on this range

    float t3    = 1.7320508075688772f * s;  // sqrt(3)*sin
    float b_hi  = 2.0f * c;
    float b_lo  = -c - t3;
    float b_mid = -c + t3;

    e0 = fmaf(p, b_lo,  q);
    e1 = fmaf(p, b_mid, q);
    e2 = fmaf(p, b_hi,  q);
}

// Issue the 9 channel cp.async loads for stage s into buffer `buf`.
// Each thread copies its own 16B per channel; no cross-thread dependency.
__device__ __forceinline__ void issue_stage(const float* __restrict__ x,
                                            float* sm, int s, int buf, int t)
{
    int b  = (s >= SPB) ? 1 : 0;           // NB == 2
    int n0 = (s - b * SPB) * CHUNK;
    const float* base = x + (size_t)b * 9 * NPB + n0 + t * 4;
    float* sbase = sm + (size_t)buf * STAGE_FLOATS + t * 4;
#pragma unroll
    for (int c = 0; c < 9; ++c) {
        unsigned sa = (unsigned)__cvta_generic_to_shared(sbase + c * CHUNK);
        asm volatile("cp.async.cg.shared.global [%0], [%1], 16;"
                     :: "r"(sa), "l"(base + (size_t)c * NPB) : "memory");
    }
}

__global__ void __launch_bounds__(BLOCK)
eigvals_kernel(const float* __restrict__ x, float* __restrict__ out)
{
    extern __shared__ float sm[];           // [PIPE][9][CHUNK]
    int t  = threadIdx.x;
    int s0 = blockIdx.x;
    int nst = (TOTAL_STAGES - s0 + GRID - 1) / GRID;  // stages for this CTA

    // Prologue: prefetch first PIPE-1 stages (one commit group per stage).
#pragma unroll
    for (int p = 0; p < PIPE - 1; ++p) {
        if (p < nst) issue_stage(x, sm, s0 + p * GRID, p, t);
        asm volatile("cp.async.commit_group;" ::: "memory");
    }

    for (int k = 0; k < nst; ++k) {
        // Oldest group (stage k) must be complete: allow PIPE-2 pending.
        asm volatile("cp.async.wait_group %0;" :: "n"(PIPE - 2) : "memory");

        int s   = s0 + k * GRID;
        int buf = k % PIPE;
        const float* sbase = sm + (size_t)buf * STAGE_FLOATS + t * 4;
        float4 v[9];
#pragma unroll
        for (int c = 0; c < 9; ++c)
            v[c] = *reinterpret_cast<const float4*>(sbase + c * CHUNK);

        // All threads done reading this buffer before it gets re-filled.
        __syncthreads();

        // Keep the DRAM queue full: issue stage k+PIPE-1 now, compute after.
        int kn = k + PIPE - 1;
        if (kn < nst) issue_stage(x, sm, s0 + kn * GRID, kn % PIPE, t);
        asm volatile("cp.async.commit_group;" ::: "memory");  // empty group OK at tail

        // Compute 4 voxels from the staged registers.
        int b  = (s >= SPB) ? 1 : 0;
        int n0 = (s - b * SPB) * CHUNK;
        float e0[4], e1[4], e2[4];
#pragma unroll
        for (int j = 0; j < 4; ++j) {
            const float* lane = reinterpret_cast<const float*>(v) + j;
            float m0 = lane[0 * 4], m1 = lane[1 * 4], m2 = lane[2 * 4];
            float m3 = lane[3 * 4], m4 = lane[4 * 4], m5 = lane[5 * 4];
            float m6 = lane[6 * 4], m7 = lane[7 * 4], m8 = lane[8 * 4];
            float s01 = 0.5f * (m1 + m3);
            float s02 = 0.5f * (m2 + m6);
            float s12 = 0.5f * (m5 + m7);
            eig3(m0, s01, s02, m4, s12, m8, e0[j], e1[j], e2[j]);
        }

        // out layout: (voxel, 3); base voxel divisible by 4 -> 16B-aligned.
        float* op = out + ((size_t)b * NPB + n0 + t * 4) * 3;
        float4 o0 = make_float4(e0[0], e1[0], e2[0], e0[1]);
        float4 o1 = make_float4(e1[1], e2[1], e0[2], e1[2]);
        float4 o2 = make_float4(e2[2], e0[3], e1[3], e2[3]);
        reinterpret_cast<float4*>(op)[0] = o0;
        reinterpret_cast<float4*>(op)[1] = o1;
        reinterpret_cast<float4*>(op)[2] = o2;
    }
}

extern "C" void kernel_launch(void* const* d_in, const int* in_sizes, int n_in,
                              void* d_out, int out_size)
{
    const float* x = (const float*)d_in[0];
    float* out = (float*)d_out;
    (void)in_sizes; (void)n_in; (void)out_size;
    static bool attr_set = false;
    if (!attr_set) {
        cudaFuncSetAttribute(eigvals_kernel,
                             cudaFuncAttributeMaxDynamicSharedMemorySize,
                             SMEM_BYTES);
        attr_set = true;
    }
    eigvals_kernel<<<GRID, BLOCK, SMEM_BYTES>>>(x, out);
}

// round 6
// speedup vs baseline: 1.0160x; 1.0160x over previous
#include <cuda_runtime.h>
#include <cuda_bf16.h>

// Problem shape (fixed): x = (2, 9, 64, 192, 192) f32
#define NPB   2359296              // voxels per batch = 64*192*192
#define NB    2
#define NVOX  (NB * NPB)           // 4,718,592
#define VPT   4                    // voxels per thread (float4 path)
#define BLOCK 256
#define NGROUPS (NVOX / VPT)       // 1,179,648 thread-groups of work
#define GPC   (NGROUPS / BLOCK)    // 4608 chunks of BLOCK groups
#define GRID  444                  // persistent: 3 CTAs/SM x 148 SMs

// Closed-form symmetric 3x3 eigenvalues (Smith's trigonometric method).
// Returns ascending e0 <= e1 <= e2.
__device__ __forceinline__ void eig3(
    float a00, float a01, float a02, float a11, float a12, float a22,
    float& e0, float& e1, float& e2)
{
    float q  = (a00 + a11 + a22) * (1.0f / 3.0f);
    float d0 = a00 - q, d1 = a11 - q, d2 = a22 - q;
    float off = a01 * a01 + a02 * a02 + a12 * a12;
    float p2  = d0 * d0 + d1 * d1 + d2 * d2 + 2.0f * off;
    p2 = fmaxf(p2, 1e-30f);                 // guard p2==0 (A == q*I)
    float p2s  = p2 * (1.0f / 6.0f);
    float pinv = rsqrtf(p2s);               // MUFU.RSQ
    float p    = p2s * pinv;                // sqrt(p2/6)

    // det(A - q*I) for the symmetrized matrix
    float det = d0 * (d1 * d2 - a12 * a12)
              - a01 * (a01 * d2 - a12 * a02)
              + a02 * (a01 * a12 - d1 * a02);

    float pinv3 = pinv * pinv * pinv;
    float r = 0.5f * det * pinv3;           // det(B)/2, B=(A-qI)/p
    r = fminf(fmaxf(r, -1.0f), 1.0f);

    float theta = acosf(r) * (1.0f / 3.0f); // theta in [0, pi/3]
    float s, c;
    __sincosf(theta, &s, &c);               // MUFU; s >= 0 on this range

    float t3    = 1.7320508075688772f * s;  // sqrt(3)*sin
    float b_hi  = 2.0f * c;                 // largest root of b^3-3b=2r
    float b_lo  = -c - t3;                  // smallest
    float b_mid = -c + t3;                  // middle

    e0 = fmaf(p, b_lo,  q);
    e1 = fmaf(p, b_mid, q);
    e2 = fmaf(p, b_hi,  q);
}

__global__ void __launch_bounds__(BLOCK)
eigvals_kernel(const float* __restrict__ x, float* __restrict__ out)
{
    const int npb4 = NPB / VPT;             // 589,824 groups per batch

    // Persistent grid-stride over the 4608 block-sized chunks.
    for (int chunk = blockIdx.x; chunk < GPC; chunk += GRID) {
        int t  = chunk * BLOCK + threadIdx.x;   // group id [0, NGROUPS)
        int b  = (t >= npb4) ? 1 : 0;           // NB == 2
        int n4 = t - b * npb4;                  // group within batch

        const float* base = x + (size_t)b * 9 * NPB + (size_t)n4 * VPT;

        // 9 channel planes, each a coalesced float4 load (front-batched).
        float4 v[9];
#pragma unroll
        for (int c = 0; c < 9; ++c)
            v[c] = *reinterpret_cast<const float4*>(base + (size_t)c * NPB);

        float e0[VPT], e1[VPT], e2[VPT];
#pragma unroll
        for (int j = 0; j < VPT; ++j) {
            const float* lane = reinterpret_cast<const float*>(v) + j;
            float m0 = lane[0 * 4], m1 = lane[1 * 4], m2 = lane[2 * 4];
            float m3 = lane[3 * 4], m4 = lane[4 * 4], m5 = lane[5 * 4];
            float m6 = lane[6 * 4], m7 = lane[7 * 4], m8 = lane[8 * 4];
            // symmetrize: channels are row-major 3x3
            float s01 = 0.5f * (m1 + m3);
            float s02 = 0.5f * (m2 + m6);
            float s12 = 0.5f * (m5 + m7);
            eig3(m0, s01, s02, m4, s12, m8, e0[j], e1[j], e2[j]);
        }

        // out layout: (voxel, 3) ascending; base voxel index divisible by 4
        // -> byte offset divisible by 48 -> 16B-aligned; 3x STG.128.
        float* op = out + ((size_t)b * NPB + (size_t)n4 * VPT) * 3;
        float4 o0 = make_float4(e0[0], e1[0], e2[0], e0[1]);
        float4 o1 = make_float4(e1[1], e2[1], e0[2], e1[2]);
        float4 o2 = make_float4(e2[2], e0[3], e1[3], e2[3]);
        reinterpret_cast<float4*>(op)[0] = o0;
        reinterpret_cast<float4*>(op)[1] = o1;
        reinterpret_cast<float4*>(op)[2] = o2;
    }
}

extern "C" void kernel_launch(void* const* d_in, const int* in_sizes, int n_in,
                              void* d_out, int out_size)
{
    const float* x = (const float*)d_in[0];
    float* out = (float*)d_out;
    (void)in_sizes; (void)n_in; (void)out_size;
    eigvals_kernel<<<GRID, BLOCK>>>(x, out);
}

// round 7
// speedup vs baseline: 1.0453x; 1.0288x over previous
#include <cuda_runtime.h>
#include <cuda_bf16.h>

// Problem shape (fixed): x = (2, 9, 64, 192, 192) f32
// Pure-streaming DRAM-bound kernel: 170 MB read + 56.6 MB write compulsory.
// Empirically optimal config (rounds 1-6): VPT=4, plain LDG/STG, one-shot grid.
#define NPB 2359296                // voxels per batch = 64*192*192
#define NB  2
#define NVOX (NB * NPB)            // 4,718,592
#define VPT 4                      // voxels per thread (float4 path)
#define NTHREADS (NVOX / VPT)      // 1,179,648
#define BLOCK 256

// Closed-form symmetric 3x3 eigenvalues (Smith's trigonometric method).
// Returns ascending e0 <= e1 <= e2.
__device__ __forceinline__ void eig3(
    float a00, float a01, float a02, float a11, float a12, float a22,
    float& e0, float& e1, float& e2)
{
    float q  = (a00 + a11 + a22) * (1.0f / 3.0f);
    float d0 = a00 - q, d1 = a11 - q, d2 = a22 - q;
    float off = a01 * a01 + a02 * a02 + a12 * a12;
    float p2  = d0 * d0 + d1 * d1 + d2 * d2 + 2.0f * off;
    p2 = fmaxf(p2, 1e-30f);                 // guard p2==0 (A == q*I)
    float p2s  = p2 * (1.0f / 6.0f);
    float pinv = rsqrtf(p2s);               // MUFU.RSQ
    float p    = p2s * pinv;                // sqrt(p2/6)

    // det(A - q*I) for the symmetrized matrix
    float det = d0 * (d1 * d2 - a12 * a12)
              - a01 * (a01 * d2 - a12 * a02)
              + a02 * (a01 * a12 - d1 * a02);

    float pinv3 = pinv * pinv * pinv;
    float r = 0.5f * det * pinv3;           // det(B)/2, B=(A-qI)/p
    r = fminf(fmaxf(r, -1.0f), 1.0f);

    float theta = acosf(r) * (1.0f / 3.0f); // theta in [0, pi/3]
    float s, c;
    __sincosf(theta, &s, &c);               // MUFU; s >= 0 on this range

    float t3    = 1.7320508075688772f * s;  // sqrt(3)*sin
    float b_hi  = 2.0f * c;                 // largest root of b^3-3b=2r
    float b_lo  = -c - t3;                  // smallest
    float b_mid = -c + t3;                  // middle

    e0 = fmaf(p, b_lo,  q);
    e1 = fmaf(p, b_mid, q);
    e2 = fmaf(p, b_hi,  q);
}

__global__ void __launch_bounds__(BLOCK)
eigvals_kernel(const float* __restrict__ x, float* __restrict__ out)
{
    int t = blockIdx.x * BLOCK + threadIdx.x;      // [0, NTHREADS)
    const int npb4 = NPB / VPT;                    // 589,824
    int b  = (t >= npb4) ? 1 : 0;                  // NB == 2
    int n4 = t - b * npb4;                         // voxel-group within batch

    const float* base = x + (size_t)b * 9 * NPB + (size_t)n4 * VPT;

    // 9 channel planes, each a coalesced float4 load (front-batched: MLP=9)
    float4 v[9];
#pragma unroll
    for (int c = 0; c < 9; ++c)
        v[c] = *reinterpret_cast<const float4*>(base + (size_t)c * NPB);

    float e0[VPT], e1[VPT], e2[VPT];
#pragma unroll
    for (int j = 0; j < VPT; ++j) {
        const float* lane = reinterpret_cast<const float*>(v) + j; // stride 4 per channel
        float m0 = lane[0 * 4], m1 = lane[1 * 4], m2 = lane[2 * 4];
        float m3 = lane[3 * 4], m4 = lane[4 * 4], m5 = lane[5 * 4];
        float m6 = lane[6 * 4], m7 = lane[7 * 4], m8 = lane[8 * 4];
        // symmetrize: channels are row-major 3x3
        float s01 = 0.5f * (m1 + m3);
        float s02 = 0.5f * (m2 + m6);
        float s12 = 0.5f * (m5 + m7);
        eig3(m0, s01, s02, m4, s12, m8, e0[j], e1[j], e2[j]);
    }

    // out layout: (voxel, 3) ascending; base voxel index divisible by 4
    // -> byte offset divisible by 48 -> 16B-aligned; 3x STG.128.
    float* op = out + ((size_t)b * NPB + (size_t)n4 * VPT) * 3;
    float4 o0 = make_float4(e0[0], e1[0], e2[0], e0[1]);
    float4 o1 = make_float4(e1[1], e2[1], e0[2], e1[2]);
    float4 o2 = make_float4(e2[2], e0[3], e1[3], e2[3]);
    reinterpret_cast<float4*>(op)[0] = o0;
    reinterpret_cast<float4*>(op)[1] = o1;
    reinterpret_cast<float4*>(op)[2] = o2;
}

extern "C" void kernel_launch(void* const* d_in, const int* in_sizes, int n_in,
                              void* d_out, int out_size)
{
    const float* x = (const float*)d_in[0];
    float* out = (float*)d_out;
    (void)in_sizes; (void)n_in; (void)out_size;
    eigvals_kernel<<<NTHREADS / BLOCK, BLOCK>>>(x, out);
}